// round 3
// baseline (speedup 1.0000x reference)
#include <cuda_runtime.h>

// Problem constants (fixed by the reference)
#define MUL  16
#define SOUTN 8
#define P3N  8
#define P4N  4

constexpr int EPB     = 16;   // edges per block (8 lanes per edge)
constexpr int THREADS = 128;
constexpr int ES      = 232;  // per-edge scratch stride in floats; 232 mod 32 == 8 -> the 4 groups
                              // in a warp start on bank quads 0/8/16/24 (conflict-free W reads)
// per-edge scratch layout: [0,32) x1 row; [32,160) W3[p][i][k]; [160,224) W4[p][i][m]

__global__ __launch_bounds__(THREADS, 8)
void tp_kernel(const float* __restrict__ x0,
               const int*   __restrict__ i0,
               const float* __restrict__ x1,
               const float* __restrict__ C3,
               const float* __restrict__ C4,
               const int*   __restrict__ p3,
               const int*   __restrict__ p4,
               float* __restrict__ out,
               int E, int nBatch)
{
    // Transposed C3: sC3T[p*64 + (i*4+k)*4 + j] -> lane reads its 4 j-values as one float4.
    __shared__ __align__(16) float sC3T[P3N * 64];
    // Transposed C4: sC4T[p*320 + (i*4+m)*20 + j*4 + k]; 20-word lane stride keeps the 8 lanes'
    // float4 reads on distinct bank quads (20l mod 32 = 0,20,8,28,16,4,24,12).
    __shared__ __align__(16) float sC4T[P4N * 320];
    __shared__ int   sp3[P3N * 3];
    __shared__ int   sp4[P4N * 4];
    __shared__ int   sCnt[SOUTN];
    __shared__ int   sList[SOUTN][P3N + P4N];   // packed: (wOffset << 8) | s0
    __shared__ __align__(16) float sEdge[EPB][ES];

    const int tid = threadIdx.x;

    // ---- stage constants (once per block), transposing for vector loads ----
    for (int idx = tid; idx < 512; idx += THREADS) {
        int p = idx >> 6, r = idx & 63;
        int i = r >> 4, j = (r >> 2) & 3, k = r & 3;
        sC3T[p * 64 + (i * 4 + k) * 4 + j] = C3[idx];
    }
    for (int idx = tid; idx < 1024; idx += THREADS) {
        int p = idx >> 8, r = idx & 255;
        int i = r >> 6, j = (r >> 4) & 3, k = (r >> 2) & 3, m = r & 3;
        sC4T[p * 320 + (i * 4 + m) * 20 + j * 4 + k] = C4[idx];
    }
    if (tid < P3N * 3) sp3[tid] = p3[tid];
    if (tid < P4N * 4) sp4[tid] = p4[tid];
    __syncthreads();

    // ---- build per-output-segment contribution lists ----
    if (tid == 0) {
        for (int so = 0; so < SOUTN; so++) {
            int c = 0;
            for (int p = 0; p < P3N; p++)
                if (sp3[p * 3 + 2] == so)
                    sList[so][c++] = ((32 + p * 16) << 8) | sp3[p * 3 + 0];
            for (int p = 0; p < P4N; p++)
                if (sp4[p * 4 + 3] == so)
                    sList[so][c++] = ((160 + p * 16) << 8) | sp4[p * 4 + 0];
            sCnt[so] = c;
        }
    }
    __syncthreads();

    const int g = tid >> 3;   // edge slot within block (0..15); 4 edges per warp
    const int l = tid & 7;    // lane within edge group; this lane owns u = l and u = l+8
    float* eg = sEdge[g];

    for (int batch = blockIdx.x; batch < nBatch; batch += gridDim.x) {
        const long long e = (long long)batch * EPB + g;
        const bool active = (e < E);

        __syncwarp();   // previous iteration's readers done before overwriting scratch

        // ---- stage x1 row (32 floats, one float4 per lane, coalesced 128B per edge) ----
        if (active) {
            const float4 v = *reinterpret_cast<const float4*>(x1 + e * 32 + l * 4);
            *reinterpret_cast<float4*>(eg + l * 4) = v;
        }
        __syncwarp();

        // ---- W3[p][i][k] = sum_j b[j] * C3[p][i][j][k]; lane covers u=l and u=l+8 ----
        #pragma unroll
        for (int p = 0; p < P3N; p++) {
            const int seg = sp3[p * 3 + 1];
            const float4 b  = *reinterpret_cast<const float4*>(eg + seg * 4);
            const float4 c0 = *reinterpret_cast<const float4*>(sC3T + p * 64 + l * 4);
            const float4 c1 = *reinterpret_cast<const float4*>(sC3T + p * 64 + (l + 8) * 4);
            eg[32 + p * 16 + l]     = b.x * c0.x + b.y * c0.y + b.z * c0.z + b.w * c0.w;
            eg[32 + p * 16 + l + 8] = b.x * c1.x + b.y * c1.y + b.z * c1.z + b.w * c1.w;
        }
        // ---- W4[p][i][m] = sum_{j,k} b[j] c[k] * C4[p][i][j][k][m] ----
        #pragma unroll
        for (int p = 0; p < P4N; p++) {
            const float4 b = *reinterpret_cast<const float4*>(eg + sp4[p * 4 + 1] * 4);
            const float4 c = *reinterpret_cast<const float4*>(eg + sp4[p * 4 + 2] * 4);
            #pragma unroll
            for (int h = 0; h < 2; h++) {                 // u = l, then u = l+8
                const int uu = l + h * 8;
                const float* q = sC4T + p * 320 + uu * 20;
                const float4 q0 = *reinterpret_cast<const float4*>(q);
                const float4 q1 = *reinterpret_cast<const float4*>(q + 4);
                const float4 q2 = *reinterpret_cast<const float4*>(q + 8);
                const float4 q3 = *reinterpret_cast<const float4*>(q + 12);
                float w = b.x * (c.x * q0.x + c.y * q0.y + c.z * q0.z + c.w * q0.w);
                w      += b.y * (c.x * q1.x + c.y * q1.y + c.z * q1.z + c.w * q1.w);
                w      += b.z * (c.x * q2.x + c.y * q2.y + c.z * q2.z + c.w * q2.w);
                w      += b.w * (c.x * q3.x + c.y * q3.y + c.z * q3.z + c.w * q3.w);
                eg[160 + p * 16 + uu] = w;
            }
        }
        __syncwarp();

        // ---- main contraction: each lane does rows u=l and u=l+8, sharing the W loads ----
        if (active) {
            const long long xbase = (long long)__ldg(i0 + e) * 512;
            const float* xr0 = x0 + xbase + l * 4;        // row u = l
            const float* xr1 = x0 + xbase + l * 4 + 32;   // row u = l+8
            float* op = out + e * 512 + l * 4;
            #pragma unroll
            for (int so = 0; so < SOUTN; so++) {
                float4 a0 = make_float4(0.f, 0.f, 0.f, 0.f);
                float4 a1 = make_float4(0.f, 0.f, 0.f, 0.f);
                const int n = sCnt[so];
                for (int t = 0; t < n; t++) {             // uniform across warp
                    const int ent = sList[so][t];
                    const int s0  = ent & 0xFF;
                    const int wo  = ent >> 8;
                    const float4 v0 = __ldg(reinterpret_cast<const float4*>(xr0 + s0 * 64));
                    const float4 v1 = __ldg(reinterpret_cast<const float4*>(xr1 + s0 * 64));
                    const float4 w0 = *reinterpret_cast<const float4*>(eg + wo);
                    const float4 w1 = *reinterpret_cast<const float4*>(eg + wo + 4);
                    const float4 w2 = *reinterpret_cast<const float4*>(eg + wo + 8);
                    const float4 w3 = *reinterpret_cast<const float4*>(eg + wo + 12);
                    a0.x += v0.x*w0.x + v0.y*w1.x + v0.z*w2.x + v0.w*w3.x;
                    a0.y += v0.x*w0.y + v0.y*w1.y + v0.z*w2.y + v0.w*w3.y;
                    a0.z += v0.x*w0.z + v0.y*w1.z + v0.z*w2.z + v0.w*w3.z;
                    a0.w += v0.x*w0.w + v0.y*w1.w + v0.z*w2.w + v0.w*w3.w;
                    a1.x += v1.x*w0.x + v1.y*w1.x + v1.z*w2.x + v1.w*w3.x;
                    a1.y += v1.x*w0.y + v1.y*w1.y + v1.z*w2.y + v1.w*w3.y;
                    a1.z += v1.x*w0.z + v1.y*w1.z + v1.z*w2.z + v1.w*w3.z;
                    a1.w += v1.x*w0.w + v1.y*w1.w + v1.z*w2.w + v1.w*w3.w;
                }
                // streaming stores: keep the 205MB output stream from evicting x0 in L2
                __stcs(reinterpret_cast<float4*>(op + so * 64), a0);
                __stcs(reinterpret_cast<float4*>(op + so * 64 + 32), a1);
            }
        }
    }
}

extern "C" void kernel_launch(void* const* d_in, const int* in_sizes, int n_in,
                              void* d_out, int out_size)
{
    const float* x0 = (const float*)d_in[0];
    const int*   i0 = (const int*)  d_in[1];
    const float* x1 = (const float*)d_in[2];
    const float* C3 = (const float*)d_in[3];
    const float* C4 = (const float*)d_in[4];
    const int*   p3 = (const int*)  d_in[5];
    const int*   p4 = (const int*)  d_in[6];
    float* out = (float*)d_out;

    const int E = in_sizes[1];                    // i0 element count = number of edges
    const int nBatch = (E + EPB - 1) / EPB;
    int grid = nBatch < 3125 ? nBatch : 3125;     // ~2 batches per block, balanced
    tp_kernel<<<grid, THREADS>>>(x0, i0, x1, C3, C4, p3, p4, out, E, nBatch);
}

// round 4
// speedup vs baseline: 1.4557x; 1.4557x over previous
#include <cuda_runtime.h>

// Problem constants (fixed by the reference)
#define SOUTN 8
#define P3N  8
#define P4N  4
#define NENT (P3N + P4N)   // 12 path entries total

constexpr int EPB     = 8;    // edges per block (16 lanes per edge) -- proven R2 layout
constexpr int THREADS = 128;
constexpr int ES      = 240;  // per-edge scratch stride in floats
// per-edge scratch layout: [0,32) x1 row; [32,160) W3[p][i][k]; [160,224) W4[p][i][m]

__global__ __launch_bounds__(THREADS, 8)
void tp_kernel(const float* __restrict__ x0,
               const int*   __restrict__ i0,
               const float* __restrict__ x1,
               const float* __restrict__ C3,
               const float* __restrict__ C4,
               const int*   __restrict__ p3,
               const int*   __restrict__ p4,
               float* __restrict__ out,
               int E, int nBatch)
{
    // Transposed C3: sC3T[p*64 + (i*4+k)*4 + j] -> lane (i,k) reads its 4 j-values as one float4.
    __shared__ __align__(16) float sC3T[P3N * 64];
    // Transposed C4: sC4T[p*320 + (i*4+m)*20 + j*4 + k]; 20-word lane stride spreads bank quads.
    __shared__ __align__(16) float sC4T[P4N * 320];
    __shared__ int   sp3[P3N * 3];
    __shared__ int   sp4[P4N * 4];
    __shared__ int   sFlat[NENT];   // (wOffset<<16) | (s0<<8) | so, sorted by so
    __shared__ int   sMasks[2];     // [0]=flushMask (bit t: store after entry t), [1]=zeroMask (bit so: no entries)
    __shared__ __align__(16) float sEdge[EPB][ES];

    const int tid = threadIdx.x;

    // ---- stage constants (once per block), transposing for vector loads ----
    for (int idx = tid; idx < 512; idx += THREADS) {
        int p = idx >> 6, r = idx & 63;
        int i = r >> 4, j = (r >> 2) & 3, k = r & 3;
        sC3T[p * 64 + (i * 4 + k) * 4 + j] = C3[idx];
    }
    for (int idx = tid; idx < 1024; idx += THREADS) {
        int p = idx >> 8, r = idx & 255;
        int i = r >> 6, j = (r >> 4) & 3, k = (r >> 2) & 3, m = r & 3;
        sC4T[p * 320 + (i * 4 + m) * 20 + j * 4 + k] = C4[idx];
    }
    if (tid < P3N * 3) sp3[tid] = p3[tid];
    if (tid < P4N * 4) sp4[tid] = p4[tid];
    __syncthreads();

    // ---- build flat entry list sorted by output segment + flush/zero masks ----
    if (tid == 0) {
        int c = 0, fm = 0, zm = 0;
        for (int so = 0; so < SOUTN; so++) {
            const int start = c;
            for (int p = 0; p < P3N; p++)
                if (sp3[p * 3 + 2] == so)
                    sFlat[c++] = ((32 + p * 16) << 16) | (sp3[p * 3 + 0] << 8) | so;
            for (int p = 0; p < P4N; p++)
                if (sp4[p * 4 + 3] == so)
                    sFlat[c++] = ((160 + p * 16) << 16) | (sp4[p * 4 + 0] << 8) | so;
            if (c > start) fm |= 1 << (c - 1);
            else           zm |= 1 << so;
        }
        sMasks[0] = fm; sMasks[1] = zm;
    }
    __syncthreads();

    // Cache block-constant entry metadata in (uniform) registers.
    int ents[NENT];
    #pragma unroll
    for (int t = 0; t < NENT; t++) ents[t] = sFlat[t];
    const unsigned flushMask = (unsigned)sMasks[0];
    const unsigned zeroMask  = (unsigned)sMasks[1];

    const int g = tid >> 4;   // edge slot within block (0..7)
    const int u = tid & 15;   // MUL index
    float* eg = sEdge[g];

    for (int batch = blockIdx.x; batch < nBatch; batch += gridDim.x) {
        const long long e = (long long)batch * EPB + g;
        const bool active = (e < E);

        __syncwarp();   // previous iteration's readers done before overwriting scratch

        // gather index early: its latency is hidden behind x1 stage + W build
        const int idx0 = active ? __ldg(i0 + e) : 0;

        // ---- stage x1 row (32 floats, 2 per thread, coalesced) ----
        if (active) {
            const float2 v = *reinterpret_cast<const float2*>(x1 + e * 32 + u * 2);
            *reinterpret_cast<float2*>(eg + u * 2) = v;
        }
        __syncwarp();

        const float* xr = x0 + (long long)idx0 * 512 + u * 4;

        // ---- prefetch first 4 gather vectors (hidden behind W build FMAs) ----
        float4 pv0 = __ldg(reinterpret_cast<const float4*>(xr + ((ents[0] >> 8) & 0xFF) * 64));
        float4 pv1 = __ldg(reinterpret_cast<const float4*>(xr + ((ents[1] >> 8) & 0xFF) * 64));
        float4 pv2 = __ldg(reinterpret_cast<const float4*>(xr + ((ents[2] >> 8) & 0xFF) * 64));
        float4 pv3 = __ldg(reinterpret_cast<const float4*>(xr + ((ents[3] >> 8) & 0xFF) * 64));

        // ---- W3[p][i][k] = sum_j b[j] * C3[p][i][j][k]; lane u = (i,k) ----
        #pragma unroll
        for (int p = 0; p < P3N; p++) {
            const int seg = sp3[p * 3 + 1];
            const float4 b = *reinterpret_cast<const float4*>(eg + seg * 4);
            const float4 c = *reinterpret_cast<const float4*>(sC3T + p * 64 + u * 4);
            eg[32 + p * 16 + u] = b.x * c.x + b.y * c.y + b.z * c.z + b.w * c.w;
        }
        // ---- W4[p][i][m] = sum_{j,k} b[j] c[k] * C4[p][i][j][k][m]; lane u = (i,m) ----
        #pragma unroll
        for (int p = 0; p < P4N; p++) {
            const float4 b = *reinterpret_cast<const float4*>(eg + sp4[p * 4 + 1] * 4);
            const float4 c = *reinterpret_cast<const float4*>(eg + sp4[p * 4 + 2] * 4);
            const float* q = sC4T + p * 320 + u * 20;
            const float4 q0 = *reinterpret_cast<const float4*>(q);
            const float4 q1 = *reinterpret_cast<const float4*>(q + 4);
            const float4 q2 = *reinterpret_cast<const float4*>(q + 8);
            const float4 q3 = *reinterpret_cast<const float4*>(q + 12);
            float w = b.x * (c.x * q0.x + c.y * q0.y + c.z * q0.z + c.w * q0.w);
            w      += b.y * (c.x * q1.x + c.y * q1.y + c.z * q1.z + c.w * q1.w);
            w      += b.z * (c.x * q2.x + c.y * q2.y + c.z * q2.z + c.w * q2.w);
            w      += b.w * (c.x * q3.x + c.y * q3.y + c.z * q3.z + c.w * q3.w);
            eg[160 + p * 16 + u] = w;
        }
        __syncwarp();

        // ---- main contraction: flat, fully-unrolled 12-entry stream with flush stores ----
        if (active) {
            float* op = out + e * 512 + u * 4;
            float4 acc = make_float4(0.f, 0.f, 0.f, 0.f);
            #pragma unroll
            for (int t = 0; t < NENT; t++) {
                const int ent = ents[t];
                const int s0  = (ent >> 8) & 0xFF;
                const int wo  = ent >> 16;
                float4 v;
                if      (t == 0) v = pv0;
                else if (t == 1) v = pv1;
                else if (t == 2) v = pv2;
                else if (t == 3) v = pv3;
                else v = __ldg(reinterpret_cast<const float4*>(xr + s0 * 64));
                const float4 w0 = *reinterpret_cast<const float4*>(eg + wo);
                const float4 w1 = *reinterpret_cast<const float4*>(eg + wo + 4);
                const float4 w2 = *reinterpret_cast<const float4*>(eg + wo + 8);
                const float4 w3 = *reinterpret_cast<const float4*>(eg + wo + 12);
                acc.x += v.x*w0.x + v.y*w1.x + v.z*w2.x + v.w*w3.x;
                acc.y += v.x*w0.y + v.y*w1.y + v.z*w2.y + v.w*w3.y;
                acc.z += v.x*w0.z + v.y*w1.z + v.z*w2.z + v.w*w3.z;
                acc.w += v.x*w0.w + v.y*w1.w + v.z*w2.w + v.w*w3.w;
                if (flushMask & (1u << t)) {          // uniform across warp
                    __stcs(reinterpret_cast<float4*>(op + (ent & 0xFF) * 64), acc);
                    acc = make_float4(0.f, 0.f, 0.f, 0.f);
                }
            }
            // segments with no contributions must still be zeroed
            #pragma unroll
            for (int so = 0; so < SOUTN; so++)
                if (zeroMask & (1u << so))
                    __stcs(reinterpret_cast<float4*>(op + so * 64),
                           make_float4(0.f, 0.f, 0.f, 0.f));
        }
    }
}

extern "C" void kernel_launch(void* const* d_in, const int* in_sizes, int n_in,
                              void* d_out, int out_size)
{
    const float* x0 = (const float*)d_in[0];
    const int*   i0 = (const int*)  d_in[1];
    const float* x1 = (const float*)d_in[2];
    const float* C3 = (const float*)d_in[3];
    const float* C4 = (const float*)d_in[4];
    const int*   p3 = (const int*)  d_in[5];
    const int*   p4 = (const int*)  d_in[6];
    float* out = (float*)d_out;

    const int E = in_sizes[1];                    // i0 element count = number of edges
    const int nBatch = (E + EPB - 1) / EPB;
    int grid = nBatch < 4624 ? nBatch : 4624;     // grid-stride, ~2.7 batches per block
    tp_kernel<<<grid, THREADS>>>(x0, i0, x1, C3, C4, p3, p4, out, E, nBatch);
}